// round 1
// baseline (speedup 1.0000x reference)
#include <cuda_runtime.h>
#include <math.h>

// ---------------- problem dims ----------------
#define Bv   2
#define Sv   1024
#define Dv   1024
#define Hh   16
#define HDv  64
#define Tv   1024
#define FFv  4096
#define Lv   8
#define Vv   32000
#define BS   (Bv*Sv)     // 2048
#define BHv  (Bv*Hh)     // 32

// ---------------- scratch (device globals; no allocations) ----------------
__device__ float g_X [BS*Dv];        // residual stream         8 MB
__device__ float g_Hb[BS*Dv];        // layernorm output        8 MB
__device__ float g_U [BS*3*Tv];      // qkv projection          24 MB
__device__ float g_Q [BHv*Sv*HDv];   // 8 MB
__device__ float g_K [BHv*Sv*HDv];   // 8 MB
__device__ float g_V [BHv*Sv*HDv];   // 8 MB
__device__ float g_P [(size_t)BHv*Sv*Sv]; // scores/probs      128 MB
__device__ float g_AO[BS*Tv];        // attention out (merged)  8 MB
__device__ float g_FH[BS*FFv];       // ffn hidden              32 MB

// ---------------- reductions ----------------
__device__ __forceinline__ float block_sum(float v, float* red) {
    #pragma unroll
    for (int o = 16; o; o >>= 1) v += __shfl_xor_sync(0xffffffffu, v, o);
    if ((threadIdx.x & 31) == 0) red[threadIdx.x >> 5] = v;
    __syncthreads();
    float t = 0.f;
    #pragma unroll
    for (int w = 0; w < 8; w++) t += red[w];
    __syncthreads();
    return t;
}
__device__ __forceinline__ float block_max(float v, float* red) {
    #pragma unroll
    for (int o = 16; o; o >>= 1) v = fmaxf(v, __shfl_xor_sync(0xffffffffu, v, o));
    if ((threadIdx.x & 31) == 0) red[threadIdx.x >> 5] = v;
    __syncthreads();
    float t = -1e30f;
    #pragma unroll
    for (int w = 0; w < 8; w++) t = fmaxf(t, red[w]);
    __syncthreads();
    return t;
}

// ---------------- embedding gather ----------------
__global__ void __launch_bounds__(256) embed_k(const int* __restrict__ ids,
                                               const float* __restrict__ emb,
                                               float* __restrict__ X) {
    int r = blockIdx.x;
    int id = ids[r];
    float4 v = ((const float4*)(emb + (size_t)id * Dv))[threadIdx.x];
    ((float4*)(X + (size_t)r * Dv))[threadIdx.x] = v;
}

// ---------------- layernorm (row of 1024, 256 thr) ----------------
__global__ void __launch_bounds__(256) layernorm_k(const float* __restrict__ in,
                                                   const float* __restrict__ w,
                                                   const float* __restrict__ b,
                                                   float* __restrict__ out) {
    __shared__ float red[8];
    int r = blockIdx.x, tid = threadIdx.x;
    float4 v = ((const float4*)(in + (size_t)r * Dv))[tid];
    float s = block_sum(v.x + v.y + v.z + v.w, red);
    float mu = s * (1.0f / Dv);
    float dx = v.x - mu, dy = v.y - mu, dz = v.z - mu, dw = v.w - mu;
    float sq = block_sum(dx*dx + dy*dy + dz*dz + dw*dw, red);
    float inv = rsqrtf(sq * (1.0f / Dv) + 1e-5f);
    float4 wv = ((const float4*)w)[tid];
    float4 bv = ((const float4*)b)[tid];
    float4 o;
    o.x = dx * inv * wv.x + bv.x;
    o.y = dy * inv * wv.y + bv.y;
    o.z = dz * inv * wv.z + bv.z;
    o.w = dw * inv * wv.w + bv.w;
    ((float4*)(out + (size_t)r * Dv))[tid] = o;
}

// ---------------- generic NT SGEMM: C = A(MxK) * B(NxK)^T ----------------
// 128x128x16 tile, 8x8 microtile, 256 threads. Optional bias/gelu/residual.
template<bool BIAS, bool GELU, bool RES>
__global__ void __launch_bounds__(256) gemm_nt(const float* __restrict__ A,
                                               const float* __restrict__ Bw,
                                               const float* __restrict__ bias,
                                               const float* __restrict__ res,
                                               float* __restrict__ C,
                                               int M, int N, int K) {
    const int BM = 128, BN = 128, BK = 16;
    __shared__ float As[BK][BM + 4];
    __shared__ float Bs[BK][BN + 4];
    int tid = threadIdx.x;
    int m0 = blockIdx.y * BM, n0 = blockIdx.x * BN;
    int tx = tid & 15, ty = tid >> 4;
    int lr = tid >> 2;          // 0..63
    int lc = (tid & 3) * 4;     // 0,4,8,12

    float acc[8][8];
    #pragma unroll
    for (int i = 0; i < 8; i++)
        #pragma unroll
        for (int j = 0; j < 8; j++) acc[i][j] = 0.f;

    for (int k0 = 0; k0 < K; k0 += BK) {
        #pragma unroll
        for (int p = 0; p < 2; p++) {
            int row = lr + p * 64;
            float4 va = *(const float4*)&A [(size_t)(m0 + row) * K + k0 + lc];
            As[lc+0][row] = va.x; As[lc+1][row] = va.y;
            As[lc+2][row] = va.z; As[lc+3][row] = va.w;
            float4 vb = *(const float4*)&Bw[(size_t)(n0 + row) * K + k0 + lc];
            Bs[lc+0][row] = vb.x; Bs[lc+1][row] = vb.y;
            Bs[lc+2][row] = vb.z; Bs[lc+3][row] = vb.w;
        }
        __syncthreads();
        #pragma unroll
        for (int kk = 0; kk < BK; kk++) {
            float ra[8], rb[8];
            #pragma unroll
            for (int i = 0; i < 8; i++) ra[i] = As[kk][ty * 8 + i];
            #pragma unroll
            for (int j = 0; j < 8; j++) rb[j] = Bs[kk][tx * 8 + j];
            #pragma unroll
            for (int i = 0; i < 8; i++)
                #pragma unroll
                for (int j = 0; j < 8; j++)
                    acc[i][j] = fmaf(ra[i], rb[j], acc[i][j]);
        }
        __syncthreads();
    }

    #pragma unroll
    for (int i = 0; i < 8; i++) {
        int m = m0 + ty * 8 + i;
        #pragma unroll
        for (int j = 0; j < 8; j++) {
            int n = n0 + tx * 8 + j;
            float v = acc[i][j];
            if (BIAS) v += bias[n];
            if (GELU) v = 0.5f * v * (1.0f + erff(v * 0.70710678118654752f));
            if (RES)  v += res[(size_t)m * N + n];
            C[(size_t)m * N + n] = v;
        }
    }
}

// ---------------- qkv split + rope ----------------
__global__ void __launch_bounds__(256) qkv_rope_k(float* __restrict__ Q,
                                                  float* __restrict__ K,
                                                  float* __restrict__ V,
                                                  const float* __restrict__ U) {
    int idx = blockIdx.x * 256 + threadIdx.x;      // bh*65536 + s*64 + d
    int d  = idx & 63;
    int s  = (idx >> 6) & (Sv - 1);
    int bh = idx >> 16;
    int b = bh >> 4, h = bh & 15;
    const float* u = U + ((size_t)(b * Sv + s)) * (3 * Tv) + h * 64;
    float uq = u[d], uk = u[Tv + d], uv = u[2 * Tv + d];
    int i  = d & 31;
    int d2 = (d < 32) ? d + 32 : d - 32;
    float uq2 = u[d2], uk2 = u[Tv + d2];
    float invf = powf(10000.0f, -(float)i / 32.0f);
    float ang = (float)s * invf;
    float c, sn;
    sincosf(ang, &sn, &c);
    float sgn = (d < 32) ? -1.0f : 1.0f;
    Q[idx] = uq * c + sgn * uq2 * sn;
    K[idx] = uk * c + sgn * uk2 * sn;
    V[idx] = uv;
}

// ---------------- attention scores: P = Q K^T / 8 (causal tile skip) ----------------
__global__ void __launch_bounds__(256) attn_scores_k(const float* __restrict__ Q,
                                                     const float* __restrict__ K,
                                                     float* __restrict__ P) {
    int bh = blockIdx.z;
    int q0 = blockIdx.y * 64, k0 = blockIdx.x * 64;
    if (k0 > q0 + 63) return;   // fully masked tile
    const float* Qp = Q + (size_t)bh * Sv * HDv;
    const float* Kp = K + (size_t)bh * Sv * HDv;
    __shared__ float Qs[16][68], Ks[16][68];
    int tid = threadIdx.x, tx = tid & 15, ty = tid >> 4;
    int lr = tid >> 2, lc = (tid & 3) * 4;
    float acc[4][4];
    #pragma unroll
    for (int i = 0; i < 4; i++)
        #pragma unroll
        for (int j = 0; j < 4; j++) acc[i][j] = 0.f;

    for (int c0 = 0; c0 < HDv; c0 += 16) {
        float4 va = *(const float4*)&Qp[(size_t)(q0 + lr) * HDv + c0 + lc];
        Qs[lc+0][lr] = va.x; Qs[lc+1][lr] = va.y; Qs[lc+2][lr] = va.z; Qs[lc+3][lr] = va.w;
        float4 vb = *(const float4*)&Kp[(size_t)(k0 + lr) * HDv + c0 + lc];
        Ks[lc+0][lr] = vb.x; Ks[lc+1][lr] = vb.y; Ks[lc+2][lr] = vb.z; Ks[lc+3][lr] = vb.w;
        __syncthreads();
        #pragma unroll
        for (int kk = 0; kk < 16; kk++) {
            float ra[4], rb[4];
            #pragma unroll
            for (int i = 0; i < 4; i++) ra[i] = Qs[kk][ty * 4 + i];
            #pragma unroll
            for (int j = 0; j < 4; j++) rb[j] = Ks[kk][tx * 4 + j];
            #pragma unroll
            for (int i = 0; i < 4; i++)
                #pragma unroll
                for (int j = 0; j < 4; j++)
                    acc[i][j] = fmaf(ra[i], rb[j], acc[i][j]);
        }
        __syncthreads();
    }
    float* out = P + (size_t)bh * Sv * Sv;
    #pragma unroll
    for (int i = 0; i < 4; i++)
        #pragma unroll
        for (int j = 0; j < 4; j++)
            out[(size_t)(q0 + ty * 4 + i) * Sv + k0 + tx * 4 + j] = acc[i][j] * 0.125f;
}

// ---------------- causal softmax over row q (len = q+1), zero-fill rest ----------------
__global__ void __launch_bounds__(256) attn_softmax_k(float* __restrict__ P) {
    __shared__ float red[8];
    int idx = blockIdx.x;            // bh*S + q
    int q = idx & (Sv - 1);
    float* row = P + (size_t)idx * Sv;
    int len = q + 1;
    int tid = threadIdx.x;
    float mx = -1e30f;
    for (int k = tid; k < len; k += 256) mx = fmaxf(mx, row[k]);
    mx = block_max(mx, red);
    float sum = 0.f;
    for (int k = tid; k < len; k += 256) {
        float e = expf(row[k] - mx);
        row[k] = e;
        sum += e;
    }
    sum = block_sum(sum, red);
    float inv = 1.0f / sum;
    for (int k = tid; k < Sv; k += 256)
        row[k] = (k < len) ? row[k] * inv : 0.0f;
}

// ---------------- PV: out = P(SxS) @ V(SxHD), head-merge epilogue ----------------
__global__ void __launch_bounds__(256) attn_pv_k(const float* __restrict__ P,
                                                 const float* __restrict__ V,
                                                 float* __restrict__ AO) {
    int bh = blockIdx.z;
    int m0 = blockIdx.y * 64;
    const float* Pp = P + (size_t)bh * Sv * Sv;
    const float* Vp = V + (size_t)bh * Sv * HDv;
    __shared__ float Ps[16][68];   // [k][m]
    __shared__ float Vs[16][68];   // [k][n]
    int tid = threadIdx.x, tx = tid & 15, ty = tid >> 4;
    int lr = tid >> 2, lc = (tid & 3) * 4;   // P loads
    int vr = tid >> 4, vc = (tid & 15) * 4;  // V loads
    float acc[4][4];
    #pragma unroll
    for (int i = 0; i < 4; i++)
        #pragma unroll
        for (int j = 0; j < 4; j++) acc[i][j] = 0.f;

    int kmax = m0 + 64;   // causal: probs zero beyond row index
    for (int k0 = 0; k0 < kmax; k0 += 16) {
        float4 va = *(const float4*)&Pp[(size_t)(m0 + lr) * Sv + k0 + lc];
        Ps[lc+0][lr] = va.x; Ps[lc+1][lr] = va.y; Ps[lc+2][lr] = va.z; Ps[lc+3][lr] = va.w;
        float4 vb = *(const float4*)&Vp[(size_t)(k0 + vr) * HDv + vc];
        Vs[vr][vc+0] = vb.x; Vs[vr][vc+1] = vb.y; Vs[vr][vc+2] = vb.z; Vs[vr][vc+3] = vb.w;
        __syncthreads();
        #pragma unroll
        for (int kk = 0; kk < 16; kk++) {
            float ra[4], rb[4];
            #pragma unroll
            for (int i = 0; i < 4; i++) ra[i] = Ps[kk][ty * 4 + i];
            #pragma unroll
            for (int j = 0; j < 4; j++) rb[j] = Vs[kk][tx * 4 + j];
            #pragma unroll
            for (int i = 0; i < 4; i++)
                #pragma unroll
                for (int j = 0; j < 4; j++)
                    acc[i][j] = fmaf(ra[i], rb[j], acc[i][j]);
        }
        __syncthreads();
    }
    int b = bh >> 4, h = bh & 15;
    #pragma unroll
    for (int i = 0; i < 4; i++) {
        int s = m0 + ty * 4 + i;
        #pragma unroll
        for (int j = 0; j < 4; j++)
            AO[((size_t)(b * Sv + s)) * Tv + h * 64 + tx * 4 + j] = acc[i][j];
    }
}

// ---------------- launch ----------------
extern "C" void kernel_launch(void* const* d_in, const int* in_sizes, int n_in,
                              void* d_out, int out_size) {
    const int*   ids = (const int*)  d_in[0];
    const float* emb = (const float*)d_in[1];
    const float* Wu  = (const float*)d_in[2];
    const float* Wo  = (const float*)d_in[3];
    const float* n1w = (const float*)d_in[4];
    const float* n1b = (const float*)d_in[5];
    const float* n2w = (const float*)d_in[6];
    const float* n2b = (const float*)d_in[7];
    const float* f1w = (const float*)d_in[8];
    const float* f1b = (const float*)d_in[9];
    const float* f2w = (const float*)d_in[10];
    const float* f2b = (const float*)d_in[11];
    const float* fnw = (const float*)d_in[12];
    const float* fnb = (const float*)d_in[13];
    float* out = (float*)d_out;

    float *X, *Hb, *U, *Q, *K, *V, *P, *AO, *FH;
    cudaGetSymbolAddress((void**)&X,  g_X);
    cudaGetSymbolAddress((void**)&Hb, g_Hb);
    cudaGetSymbolAddress((void**)&U,  g_U);
    cudaGetSymbolAddress((void**)&Q,  g_Q);
    cudaGetSymbolAddress((void**)&K,  g_K);
    cudaGetSymbolAddress((void**)&V,  g_V);
    cudaGetSymbolAddress((void**)&P,  g_P);
    cudaGetSymbolAddress((void**)&AO, g_AO);
    cudaGetSymbolAddress((void**)&FH, g_FH);

    embed_k<<<BS, 256>>>(ids, emb, X);

    for (int l = 0; l < Lv; l++) {
        // ---- attention block ----
        layernorm_k<<<BS, 256>>>(X, n1w + l * Dv, n1b + l * Dv, Hb);
        gemm_nt<false, false, false><<<dim3(3 * Tv / 128, BS / 128), 256>>>(
            Hb, Wu + (size_t)l * 3 * Tv * Dv, nullptr, nullptr, U, BS, 3 * Tv, Dv);
        qkv_rope_k<<<(BHv * Sv * HDv) / 256, 256>>>(Q, K, V, U);
        attn_scores_k<<<dim3(Sv / 64, Sv / 64, BHv), 256>>>(Q, K, P);
        attn_softmax_k<<<BHv * Sv, 256>>>(P);
        attn_pv_k<<<dim3(1, Sv / 64, BHv), 256>>>(P, V, AO);
        gemm_nt<false, false, true><<<dim3(Dv / 128, BS / 128), 256>>>(
            AO, Wo + (size_t)l * Dv * Tv, nullptr, X, X, BS, Dv, Tv);

        // ---- mlp block ----
        layernorm_k<<<BS, 256>>>(X, n2w + l * Dv, n2b + l * Dv, Hb);
        gemm_nt<true, true, false><<<dim3(FFv / 128, BS / 128), 256>>>(
            Hb, f1w + (size_t)l * FFv * Dv, f1b + (size_t)l * FFv, nullptr, FH, BS, FFv, Dv);
        gemm_nt<true, false, true><<<dim3(Dv / 128, BS / 128), 256>>>(
            FH, f2w + (size_t)l * Dv * FFv, f2b + (size_t)l * Dv, X, X, BS, Dv, FFv);
    }

    // ---- final LN + tied-embedding logits ----
    layernorm_k<<<BS, 256>>>(X, fnw, fnb, Hb);
    gemm_nt<false, false, false><<<dim3(Vv / 128, BS / 128), 256>>>(
        Hb, emb, nullptr, nullptr, out, BS, Vv, Dv);
}